// round 1
// baseline (speedup 1.0000x reference)
#include <cuda_runtime.h>
#include <math.h>

#define NLEV 16
#define MAX_SIZE (1u << 19)

struct LP {
    float    res[NLEV];
    unsigned mask[NLEV];
};

__global__ void __launch_bounds__(256)
hashgrid_kernel(const float* __restrict__ x,
                const float* __restrict__ tables,
                float* __restrict__ out,
                LP lp, int n)
{
    int i = blockIdx.x * blockDim.x + threadIdx.x;
    if (i >= n) return;

    const float px = x[3 * i + 0];
    const float py = x[3 * i + 1];
    const float pz = x[3 * i + 2];

    float4* out4 = reinterpret_cast<float4*>(out) + (size_t)i * 8;

#pragma unroll
    for (int lpair = 0; lpair < NLEV / 2; ++lpair) {
        float2 accs[2];
#pragma unroll
        for (int s = 0; s < 2; ++s) {
            const int l = 2 * lpair + s;
            const float    res  = lp.res[l];
            const unsigned mask = lp.mask[l];
            const float2* __restrict__ tbl =
                reinterpret_cast<const float2*>(tables) + (size_t)l * MAX_SIZE;

            const float xs = px * res, ys = py * res, zs = pz * res;
            const float fx = floorf(xs), fy = floorf(ys), fz = floorf(zs);
            const unsigned ix = (unsigned)fx, iy = (unsigned)fy, iz = (unsigned)fz;
            const float wx1 = xs - fx, wy1 = ys - fy, wz1 = zs - fz;
            const float wx0 = 1.0f - wx1, wy0 = 1.0f - wy1, wz0 = 1.0f - wz1;

            // primes: dim0 = 1, dim1 = 2654435761, dim2 = 805459861 (u32 wrap)
            const unsigned hx0 = ix;
            const unsigned hx1 = ix + 1u;
            const unsigned hy0 = iy * 2654435761u;
            const unsigned hy1 = hy0 + 2654435761u;
            const unsigned hz0 = iz * 805459861u;
            const unsigned hz1 = hz0 + 805459861u;

            const float wyz00 = wy0 * wz0;
            const float wyz10 = wy1 * wz0;
            const float wyz01 = wy0 * wz1;
            const float wyz11 = wy1 * wz1;

            float2 acc = make_float2(0.0f, 0.0f);

            // neighbor n: bit0 -> x, bit1 -> y, bit2 -> z; bit set = high corner (weight = xf)
#define CORNER(bx, by, bz)                                                          \
            {                                                                       \
                unsigned h = ((bx) ? hx1 : hx0) ^ ((by) ? hy1 : hy0)                \
                             ^ ((bz) ? hz1 : hz0);                                  \
                float2 f = __ldg(&tbl[h & mask]);                                   \
                float  w = ((bx) ? wx1 : wx0) *                                     \
                           ((by) ? ((bz) ? wyz11 : wyz10)                           \
                                 : ((bz) ? wyz01 : wyz00));                         \
                acc.x = fmaf(w, f.x, acc.x);                                        \
                acc.y = fmaf(w, f.y, acc.y);                                        \
            }
            CORNER(0, 0, 0)
            CORNER(1, 0, 0)
            CORNER(0, 1, 0)
            CORNER(1, 1, 0)
            CORNER(0, 0, 1)
            CORNER(1, 0, 1)
            CORNER(0, 1, 1)
            CORNER(1, 1, 1)
#undef CORNER
            accs[s] = acc;
        }
        out4[lpair] = make_float4(accs[0].x, accs[0].y, accs[1].x, accs[1].y);
    }
}

extern "C" void kernel_launch(void* const* d_in, const int* in_sizes, int n_in,
                              void* d_out, int out_size)
{
    const float* x      = (const float*)d_in[0];
    const float* tables = (const float*)d_in[1];
    float*       out    = (float*)d_out;
    const int    n      = in_sizes[0] / 3;

    // Replicate the reference's level-resolution math EXACTLY in double precision
    // (same libm as the Python reference on this host). 16*b^l sits on an integer
    // knife-edge at l=3,6,9,12,15, so floor() must match bit-for-bit.
    LP lp;
    const double b = exp((log(512.0) - log(16.0)) / 15.0);
    for (int l = 0; l < NLEV; ++l) {
        const double r   = floor(16.0 * pow(b, (double)l));
        const long   res = (long)r;
        long sz = res * res * res;
        if (sz > (1L << 19)) sz = (1L << 19);
        long p = 1;
        while (p < sz) p <<= 1;
        lp.res[l]  = (float)r;
        lp.mask[l] = (unsigned)(p - 1);
    }

    const int threads = 256;
    const int blocks  = (n + threads - 1) / threads;
    hashgrid_kernel<<<blocks, threads>>>(x, tables, out, lp, n);
}

// round 2
// speedup vs baseline: 1.5663x; 1.5663x over previous
#include <cuda_runtime.h>
#include <math.h>

#define NLEV 16
#define MAX_SIZE (1u << 19)
#define P1 2654435761u
#define P2 805459861u

struct LP {
    float    res[NLEV];
    unsigned mask[NLEV];
};

// Layout: 8 lanes per point (one per corner), 4 points per warp.
// Each level is a single warp-wide LDG.64; x-corner pairs of each point land
// in the same 32B sector ~75% / same 128B line ~94% of the time, so the L1
// wavefront count per point-level drops from 8 to ~4.25.
__global__ void __launch_bounds__(256)
hashgrid_kernel(const float* __restrict__ x,
                const float* __restrict__ tables,
                float* __restrict__ out,
                LP lp, int n)
{
    const int lane   = threadIdx.x & 31;
    const int warpid = (blockIdx.x * (blockDim.x >> 5)) + (threadIdx.x >> 5);
    const int pt     = warpid * 4 + (lane >> 3);
    if (pt >= n) return;

    const int c  = lane & 7;
    const unsigned bx = c & 1;
    const unsigned by = (c >> 1) & 1;
    const unsigned bz = (c >> 2) & 1;

    const float px = x[3 * pt + 0];
    const float py = x[3 * pt + 1];
    const float pz = x[3 * pt + 2];

    // r[j] holds this lane's stashed result for level (c + 8*j)
    float2 r[2];

#pragma unroll
    for (int l = 0; l < NLEV; ++l) {
        const float    res  = lp.res[l];
        const unsigned mask = lp.mask[l];
        const float2* __restrict__ tbl =
            reinterpret_cast<const float2*>(tables) + (size_t)l * MAX_SIZE;

        const float xs = px * res, ys = py * res, zs = pz * res;
        const float fx = floorf(xs), fy = floorf(ys), fz = floorf(zs);

        const unsigned ix = (unsigned)fx + bx;
        const unsigned iy = (unsigned)fy + by;
        const unsigned iz = (unsigned)fz + bz;

        const float xf = xs - fx, yf = ys - fy, zf = zs - fz;
        const float wx = bx ? xf : 1.0f - xf;
        const float wy = by ? yf : 1.0f - yf;
        const float wz = bz ? zf : 1.0f - zf;
        const float w  = wx * wy * wz;

        const unsigned h   = ix ^ (iy * P1) ^ (iz * P2);
        const float2   f   = __ldg(&tbl[h & mask]);

        float vx = w * f.x;
        float vy = w * f.y;

        // sum over the 8 corner lanes (butterfly stays within the 8-lane group)
#pragma unroll
        for (int m = 1; m < 8; m <<= 1) {
            vx += __shfl_xor_sync(0xffffffffu, vx, m);
            vy += __shfl_xor_sync(0xffffffffu, vy, m);
        }

        // lane c keeps levels c and c+8
        if ((l & 7) == c) r[l >> 3] = make_float2(vx, vy);
    }

    // out[pt*32 + 2*l + k]: lane c writes levels c (offset 2c) and c+8 (offset 2c+16).
    // The 8 lanes of a group cover two contiguous 64B segments per point.
    float2* o = reinterpret_cast<float2*>(out + (size_t)pt * 32);
    o[c]     = r[0];
    o[c + 8] = r[1];
}

extern "C" void kernel_launch(void* const* d_in, const int* in_sizes, int n_in,
                              void* d_out, int out_size)
{
    const float* x      = (const float*)d_in[0];
    const float* tables = (const float*)d_in[1];
    float*       out    = (float*)d_out;
    const int    n      = in_sizes[0] / 3;

    // Replicate the reference's level-resolution math EXACTLY in double precision.
    LP lp;
    const double b = exp((log(512.0) - log(16.0)) / 15.0);
    for (int l = 0; l < NLEV; ++l) {
        const double r   = floor(16.0 * pow(b, (double)l));
        const long   res = (long)r;
        long sz = res * res * res;
        if (sz > (1L << 19)) sz = (1L << 19);
        long p = 1;
        while (p < sz) p <<= 1;
        lp.res[l]  = (float)r;
        lp.mask[l] = (unsigned)(p - 1);
    }

    const int threads = 256;                 // 8 warps -> 32 points per block
    const int pts_per_block = (threads / 32) * 4;
    const int blocks = (n + pts_per_block - 1) / pts_per_block;
    hashgrid_kernel<<<blocks, threads>>>(x, tables, out, lp, n);
}